// round 9
// baseline (speedup 1.0000x reference)
#include <cuda_runtime.h>
#include <cuda_fp16.h>
#include <cstdint>
#include <cstddef>
#include <cstring>

// Problem constants (fixed by the dataset)
constexpr int Gn = 16;
constexpr int Bn = 8192;
constexpr int Kn = 1024;
constexpr int Dn = 64;

constexpr int DP  = 80;              // augmented dim: 64 data + 4 norm + 12 pad
constexpr int RB  = DP * 2;          // 160 bytes per augmented row
constexpr int TM  = 128;             // x rows per tile
constexpr int TN  = 128;             // centroids per CTA (resident)
constexpr int NBT = 4;               // x tiles per CTA
constexpr int NT  = 512;             // threads per CTA

// Augmented f16 operands (device globals: allocation-free scratch).
//  x row:  [-2x (64)] [x2_hi, x2_lo, 1, 1] [0 x 12]
//  c row:  [ c  (64)] [1, 1, c2_hi, c2_lo] [0 x 12]
__device__ __align__(16) uint32_t g_xb[(size_t)Gn * Bn * (RB / 4)];
__device__ __align__(16) uint32_t g_cb[(size_t)Gn * Kn * (RB / 4)];

// Dynamic smem layout (bytes).
constexpr int CS0 = 0;          // c main (16KB, 128B rows, XOR swizzle)
constexpr int CS1 = 16384;      // c aug  (4KB, 32B rows)
constexpr int XB0 = 20480;      // x buffer 0 (main+aug)
constexpr int XB1 = 40960;      // x buffer 1
constexpr int STG_OFF = 61440;  // epilogue staging: 128 rows x 64 cols f16 = 16KB
constexpr int SMEM_TOTAL = 77824;

__device__ __forceinline__ uint32_t smem_u32(const void* p) {
    uint32_t a;
    asm("{ .reg .u64 t; cvta.to.shared.u64 t, %1; cvt.u32.u64 %0, t; }"
        : "=r"(a) : "l"(p));
    return a;
}
__device__ __forceinline__ float fsqrt_approx(float v) {
    float r;
    asm("sqrt.approx.f32 %0, %1;" : "=f"(r) : "f"(v));
    return r;
}
__device__ __forceinline__ uint32_t pack_f16(float lo, float hi) {
    __half2 h = __floats2half2_rn(lo, hi);   // .x = lo (low half)
    uint32_t u;
    memcpy(&u, &h, 4);
    return u;
}
__device__ __forceinline__ void cp16(uint32_t dst, const void* src) {
    asm volatile("cp.async.cg.shared.global [%0], [%1], 16;"
                 :: "r"(dst), "l"(src) : "memory");
}
#define CP_COMMIT() asm volatile("cp.async.commit_group;" ::: "memory")
#define CP_WAIT0()  asm volatile("cp.async.wait_group 0;" ::: "memory")

__device__ __forceinline__ void ldsm_x4(uint32_t r[4], uint32_t addr) {
    asm volatile("ldmatrix.sync.aligned.m8n8.x4.shared.b16 {%0,%1,%2,%3}, [%4];"
                 : "=r"(r[0]), "=r"(r[1]), "=r"(r[2]), "=r"(r[3]) : "r"(addr));
}
// f16 x f16 -> f16 accumulate: D/C in 2 regs (f16x2 each)
__device__ __forceinline__ void mma_f16(uint32_t c[2], const uint32_t a[4],
                                        uint32_t b0, uint32_t b1) {
    asm volatile(
        "mma.sync.aligned.m16n8k16.row.col.f16.f16.f16.f16 "
        "{%0,%1}, {%2,%3,%4,%5}, {%6,%7}, {%0,%1};"
        : "+r"(c[0]), "+r"(c[1])
        : "r"(a[0]), "r"(a[1]), "r"(a[2]), "r"(a[3]), "r"(b0), "r"(b1));
}
__device__ __forceinline__ void stg_cs4(float* p, float a, float b, float c, float d) {
    asm volatile("st.global.cs.v4.f32 [%0], {%1, %2, %3, %4};"
                 :: "l"(p), "f"(a), "f"(b), "f"(c), "f"(d) : "memory");
}
// aug-tile address: 32B rows; 16B chunk q of row r at flat=(2r+q)^((r>>2)&7)
__device__ __forceinline__ uint32_t t1addr(uint32_t base, int row, int q) {
    return base + (uint32_t)((((row * 2 + q) ^ ((row >> 2) & 7)) << 4));
}

// ---------------------------------------------------------------------------
// Pass 1: build augmented f16 rows (exact fp32 norms, f16 hi/lo split).
// ---------------------------------------------------------------------------
__global__ __launch_bounds__(256)
void prep_kernel(const float* __restrict__ x, const float* __restrict__ cen)
{
    const int t  = blockIdx.x * blockDim.x + threadIdx.x;
    const int NX = Gn * Bn;
    const int NC = Gn * Kn;
    const float4* src;
    uint4* dst;
    bool is_x;
    if (t < NX) {
        src = (const float4*)(x + (size_t)t * Dn);
        dst = (uint4*)(g_xb + (size_t)t * (RB / 4));
        is_x = true;
    } else if (t < NX + NC) {
        src = (const float4*)(cen + (size_t)(t - NX) * Dn);
        dst = (uint4*)(g_cb + (size_t)(t - NX) * (RB / 4));
        is_x = false;
    } else return;

    const float a = is_x ? -2.0f : 1.0f;
    float s = 0.f;
#pragma unroll
    for (int i = 0; i < 8; i++) {
        float4 v0 = src[2 * i];
        float4 v1 = src[2 * i + 1];
        s = fmaf(v0.x, v0.x, s); s = fmaf(v0.y, v0.y, s);
        s = fmaf(v0.z, v0.z, s); s = fmaf(v0.w, v0.w, s);
        s = fmaf(v1.x, v1.x, s); s = fmaf(v1.y, v1.y, s);
        s = fmaf(v1.z, v1.z, s); s = fmaf(v1.w, v1.w, s);
        uint4 o;
        o.x = pack_f16(a * v0.x, a * v0.y); o.y = pack_f16(a * v0.z, a * v0.w);
        o.z = pack_f16(a * v1.x, a * v1.y); o.w = pack_f16(a * v1.z, a * v1.w);
        dst[i] = o;
    }
    // f16 hi/lo split of the squared norm
    const float hf  = __half2float(__float2half_rn(s));
    const float res = s - hf;
    uint4 aug;
    if (is_x) { aug.x = pack_f16(hf, res);   aug.y = pack_f16(1.f, 1.f); }
    else      { aug.x = pack_f16(1.f, 1.f);  aug.y = pack_f16(hf, res);  }
    aug.z = 0u; aug.w = 0u;
    dst[8] = aug;
    dst[9] = make_uint4(0u, 0u, 0u, 0u);
}

// Tile loader: 1280 16B chunks (128 rows x 160B) over 512 threads.
__device__ __forceinline__ void load_tile(uint32_t t0, uint32_t t1,
                                          const char* gsrc, int tid)
{
#pragma unroll
    for (int i = 0; i < 3; i++) {
        const int idx = i * NT + tid;
        if (idx < 1280) {
            const int row = idx / 10;
            const int q   = idx - row * 10;
            const char* src = gsrc + row * RB + q * 16;
            if (q < 8) cp16(t0 + row * 128 + ((q ^ (row & 7)) << 4), src);
            else       cp16(t1addr(t1, row, q - 8), src);
        }
    }
}

// ---------------------------------------------------------------------------
// Pass 2: 512 threads, 4x4 warps of 32x32 tiles; f16 acc == d^2.
// Epilogue is staged through smem for fully coalesced global stores.
// ---------------------------------------------------------------------------
__global__ __launch_bounds__(NT, 2)
void dist_kernel(float* __restrict__ out)
{
    extern __shared__ __align__(128) char smem[];
    const uint32_t sb = smem_u32(smem);

    const int tid  = threadIdx.x;
    const int wid  = tid >> 5;
    const int lane = tid & 31;
    const int qid  = lane >> 2;     // 0..7
    const int t4   = lane & 3;      // 0..3

    const int g     = blockIdx.z;
    const int k0    = blockIdx.x * TN;
    const int bslab = blockIdx.y * (TM * NBT);

    const char* cgb = (const char*)g_cb + (size_t)(g * Kn + k0)    * RB;
    const char* xgb = (const char*)g_xb + (size_t)(g * Bn + bslab) * RB;

    // ---- Prologue: c tile, then x tile 0. ----
    load_tile(sb + CS0, sb + CS1, cgb, tid);
    CP_COMMIT();
    load_tile(sb + XB0, sb + XB0 + 16384, xgb, tid);
    CP_COMMIT();

    const int wm = (wid >> 2) * 32;   // warp m-base: 0/32/64/96
    const int wn = (wid & 3) * 32;    // warp n-base: 0/32/64/96

    // Per-lane ldmatrix geometry.
    const int swz    = lane & 7;
    const int a_row  = lane & 15;                        // + wm + mt*16
    const int a_qoff = lane >> 4;                        // 0/1
    const int b_nrow = ((lane >> 4) << 3) + (lane & 7);  // + wn (+16)
    const int b_qoff = (lane >> 3) & 1;                  // 0/1

    // Epilogue geometry.
    const uint32_t stg = sb + STG_OFF;
    const int wpass = wn >> 6;            // which column-half this warp writes
    const int wcolw = (wn & 32) >> 1;     // staging word base: 0 or 16
    const int r_rd  = wid * 4 + (lane >> 3);   // reader row (+ rr*64)
    const int j_rd  = lane & 7;                // reader chunk (8 f16)

    for (int bt = 0; bt < NBT; bt++) {
        CP_WAIT0();
        __syncthreads();

        if (bt + 1 < NBT) {
            const char* xn = xgb + (size_t)(bt + 1) * TM * RB;
            const uint32_t base = sb + (((bt + 1) & 1) ? XB1 : XB0);
            load_tile(base, base + 16384, xn, tid);
            CP_COMMIT();
        }

        const uint32_t xs0 = sb + ((bt & 1) ? XB1 : XB0);
        const uint32_t xs1 = xs0 + 16384;
        const uint32_t cs0 = sb + CS0;
        const uint32_t cs1 = sb + CS1;

        // acc[mt][nt][h]: f16x2 pair for rows wm+16mt+8h+qid, cols wn+8nt+2t4.
        uint32_t acc[2][4][2];
#pragma unroll
        for (int mt = 0; mt < 2; mt++)
#pragma unroll
            for (int nt = 0; nt < 4; nt++) { acc[mt][nt][0] = 0u; acc[mt][nt][1] = 0u; }

        // ---- k-steps 0..3: main 64 dims. ----
#pragma unroll
        for (int ks = 0; ks < 4; ks++) {
            const uint32_t qa = (uint32_t)(((2 * ks + a_qoff) ^ swz) << 4);
            const uint32_t qb = (uint32_t)(((2 * ks + b_qoff) ^ swz) << 4);

            uint32_t bf[4][2];
            {
                uint32_t r[4];
                ldsm_x4(r, cs0 + (uint32_t)((wn + b_nrow) * 128) + qb);
                bf[0][0] = r[0]; bf[0][1] = r[1]; bf[1][0] = r[2]; bf[1][1] = r[3];
                ldsm_x4(r, cs0 + (uint32_t)((wn + 16 + b_nrow) * 128) + qb);
                bf[2][0] = r[0]; bf[2][1] = r[1]; bf[3][0] = r[2]; bf[3][1] = r[3];
            }
#pragma unroll
            for (int mt = 0; mt < 2; mt++) {
                uint32_t a[4];
                ldsm_x4(a, xs0 + (uint32_t)((wm + mt * 16 + a_row) * 128) + qa);
#pragma unroll
                for (int nt = 0; nt < 4; nt++)
                    mma_f16(acc[mt][nt], a, bf[nt][0], bf[nt][1]);
            }
        }

        // ---- k-step 4: augmented 16 dims. ----
        {
            uint32_t bf[4][2];
            {
                uint32_t r[4];
                ldsm_x4(r, t1addr(cs1, wn + b_nrow, b_qoff));
                bf[0][0] = r[0]; bf[0][1] = r[1]; bf[1][0] = r[2]; bf[1][1] = r[3];
                ldsm_x4(r, t1addr(cs1, wn + 16 + b_nrow, b_qoff));
                bf[2][0] = r[0]; bf[2][1] = r[1]; bf[3][0] = r[2]; bf[3][1] = r[3];
            }
#pragma unroll
            for (int mt = 0; mt < 2; mt++) {
                uint32_t a[4];
                ldsm_x4(a, t1addr(xs1, wm + mt * 16 + a_row, a_qoff));
#pragma unroll
                for (int nt = 0; nt < 4; nt++)
                    mma_f16(acc[mt][nt], a, bf[nt][0], bf[nt][1]);
            }
        }

        // ---- Epilogue: stage f16 d^2 in smem, read coalesced, sqrt, STG. ----
        const int b0 = bslab + bt * TM;
#pragma unroll
        for (int p = 0; p < 2; p++) {
            __syncthreads();   // staging buffer free (prev pass / prev tile read)

            if (wpass == p) {
                // Writer: 16 STS.32, conflict-free via (w ^ qid<<2) swizzle.
#pragma unroll
                for (int mt = 0; mt < 2; mt++)
#pragma unroll
                    for (int h = 0; h < 2; h++) {
                        const int row = wm + 16 * mt + 8 * h + qid;
#pragma unroll
                        for (int nt = 0; nt < 4; nt++) {
                            const int w = wcolw + 4 * nt + t4;
                            const uint32_t a = stg +
                                (uint32_t)(row * 128 + ((w ^ (qid << 2)) << 2));
                            asm volatile("st.shared.b32 [%0], %1;"
                                         :: "r"(a), "r"(acc[mt][nt][h]) : "memory");
                        }
                    }
            }
            __syncthreads();

            // Reader: all warps; 2 rounds x (LDS.128 + 8 sqrt + 2 STG.128).
#pragma unroll
            for (int rr = 0; rr < 2; rr++) {
                const int r = rr * 64 + r_rd;
                uint4 v;
                const uint32_t a = stg +
                    (uint32_t)(r * 128 + ((j_rd ^ (r & 7)) << 4));
                asm volatile("ld.shared.v4.b32 {%0,%1,%2,%3}, [%4];"
                             : "=r"(v.x), "=r"(v.y), "=r"(v.z), "=r"(v.w)
                             : "r"(a));
                __half2 h0, h1, h2, h3;
                memcpy(&h0, &v.x, 4); memcpy(&h1, &v.y, 4);
                memcpy(&h2, &v.z, 4); memcpy(&h3, &v.w, 4);
                const float2 f0 = __half22float2(h0);
                const float2 f1 = __half22float2(h1);
                const float2 f2 = __half22float2(h2);
                const float2 f3 = __half22float2(h3);
                float* op = out + (size_t)(g * Bn + b0 + r) * Kn
                                + k0 + p * 64 + 8 * j_rd;
                stg_cs4(op,
                        fsqrt_approx(f0.x), fsqrt_approx(f0.y),
                        fsqrt_approx(f1.x), fsqrt_approx(f1.y));
                stg_cs4(op + 4,
                        fsqrt_approx(f2.x), fsqrt_approx(f2.y),
                        fsqrt_approx(f3.x), fsqrt_approx(f3.y));
            }
        }
    }
}

extern "C" void kernel_launch(void* const* d_in, const int* in_sizes, int n_in,
                              void* d_out, int out_size)
{
    const float* x   = (const float*)d_in[0];   // [G, B, D] fp32
    const float* cen = (const float*)d_in[1];   // [G, K, D] fp32
    float* out = (float*)d_out;                 // [G, B, K] fp32

    static bool attr_set = false;
    if (!attr_set) {
        cudaFuncSetAttribute(dist_kernel,
                             cudaFuncAttributeMaxDynamicSharedMemorySize, SMEM_TOTAL);
        attr_set = true;
    }

    const int nrows = Gn * Bn + Gn * Kn;
    prep_kernel<<<(nrows + 255) / 256, 256>>>(x, cen);

    dim3 grid(Kn / TN, Bn / (TM * NBT), Gn);    // (8, 16, 16) = 2048 CTAs
    dist_kernel<<<grid, NT, SMEM_TOTAL>>>(out);
}

// round 10
// speedup vs baseline: 1.3950x; 1.3950x over previous
#include <cuda_runtime.h>
#include <cuda_fp16.h>
#include <cstdint>
#include <cstddef>
#include <cstring>

// Problem constants (fixed by the dataset)
constexpr int Gn = 16;
constexpr int Bn = 8192;
constexpr int Kn = 1024;
constexpr int Dn = 64;

constexpr int DP  = 80;              // augmented dim: 64 data + 4 norm + 12 pad
constexpr int RB  = DP * 2;          // 160 bytes per augmented row
constexpr int TM  = 128;             // x rows per tile
constexpr int TN  = 128;             // centroids per CTA (resident)
constexpr int NBT = 4;               // x tiles per CTA
constexpr int NT  = 512;             // threads per CTA

// Augmented f16 operands (device globals: allocation-free scratch).
//  x row:  [-2x (64)] [x2_hi, x2_lo, 1, 1] [0 x 12]
//  c row:  [ c  (64)] [1, 1, c2_hi, c2_lo] [0 x 12]
__device__ __align__(16) uint32_t g_xb[(size_t)Gn * Bn * (RB / 4)];
__device__ __align__(16) uint32_t g_cb[(size_t)Gn * Kn * (RB / 4)];

// Dynamic smem layout (bytes).
constexpr int CS0 = 0;          // c main (16KB, 128B rows, XOR swizzle)
constexpr int CS1 = 16384;      // c aug  (4KB, 32B rows)
constexpr int XB0 = 20480;      // x buffer 0 (main+aug)
constexpr int XB1 = 40960;      // x buffer 1
constexpr int STG_OFF = 61440;  // per-warp staging: 16 warps x 2KB = 32KB
constexpr int SMEM_TOTAL = 94208;

__device__ __forceinline__ uint32_t smem_u32(const void* p) {
    uint32_t a;
    asm("{ .reg .u64 t; cvta.to.shared.u64 t, %1; cvt.u32.u64 %0, t; }"
        : "=r"(a) : "l"(p));
    return a;
}
__device__ __forceinline__ float fsqrt_approx(float v) {
    float r;
    asm("sqrt.approx.f32 %0, %1;" : "=f"(r) : "f"(v));
    return r;
}
__device__ __forceinline__ uint32_t pack_f16(float lo, float hi) {
    __half2 h = __floats2half2_rn(lo, hi);   // .x = lo (low half)
    uint32_t u;
    memcpy(&u, &h, 4);
    return u;
}
__device__ __forceinline__ void cp16(uint32_t dst, const void* src) {
    asm volatile("cp.async.cg.shared.global [%0], [%1], 16;"
                 :: "r"(dst), "l"(src) : "memory");
}
#define CP_COMMIT() asm volatile("cp.async.commit_group;" ::: "memory")
#define CP_WAIT0()  asm volatile("cp.async.wait_group 0;" ::: "memory")

__device__ __forceinline__ void ldsm_x4(uint32_t r[4], uint32_t addr) {
    asm volatile("ldmatrix.sync.aligned.m8n8.x4.shared.b16 {%0,%1,%2,%3}, [%4];"
                 : "=r"(r[0]), "=r"(r[1]), "=r"(r[2]), "=r"(r[3]) : "r"(addr));
}
// f16 x f16 -> f16 accumulate: D/C in 2 regs (f16x2 each)
__device__ __forceinline__ void mma_f16(uint32_t c[2], const uint32_t a[4],
                                        uint32_t b0, uint32_t b1) {
    asm volatile(
        "mma.sync.aligned.m16n8k16.row.col.f16.f16.f16.f16 "
        "{%0,%1}, {%2,%3,%4,%5}, {%6,%7}, {%0,%1};"
        : "+r"(c[0]), "+r"(c[1])
        : "r"(a[0]), "r"(a[1]), "r"(a[2]), "r"(a[3]), "r"(b0), "r"(b1));
}
__device__ __forceinline__ void stg_cs4(float* p, float a, float b, float c, float d) {
    asm volatile("st.global.cs.v4.f32 [%0], {%1, %2, %3, %4};"
                 :: "l"(p), "f"(a), "f"(b), "f"(c), "f"(d) : "memory");
}
// aug-tile address: 32B rows; 16B chunk q of row r at flat=(2r+q)^((r>>2)&7)
__device__ __forceinline__ uint32_t t1addr(uint32_t base, int row, int q) {
    return base + (uint32_t)((((row * 2 + q) ^ ((row >> 2) & 7)) << 4));
}

// ---------------------------------------------------------------------------
// Pass 1: build augmented f16 rows (exact fp32 norms, f16 hi/lo split).
// ---------------------------------------------------------------------------
__global__ __launch_bounds__(256)
void prep_kernel(const float* __restrict__ x, const float* __restrict__ cen)
{
    const int t  = blockIdx.x * blockDim.x + threadIdx.x;
    const int NX = Gn * Bn;
    const int NC = Gn * Kn;
    const float4* src;
    uint4* dst;
    bool is_x;
    if (t < NX) {
        src = (const float4*)(x + (size_t)t * Dn);
        dst = (uint4*)(g_xb + (size_t)t * (RB / 4));
        is_x = true;
    } else if (t < NX + NC) {
        src = (const float4*)(cen + (size_t)(t - NX) * Dn);
        dst = (uint4*)(g_cb + (size_t)(t - NX) * (RB / 4));
        is_x = false;
    } else return;

    const float a = is_x ? -2.0f : 1.0f;
    float s = 0.f;
#pragma unroll
    for (int i = 0; i < 8; i++) {
        float4 v0 = src[2 * i];
        float4 v1 = src[2 * i + 1];
        s = fmaf(v0.x, v0.x, s); s = fmaf(v0.y, v0.y, s);
        s = fmaf(v0.z, v0.z, s); s = fmaf(v0.w, v0.w, s);
        s = fmaf(v1.x, v1.x, s); s = fmaf(v1.y, v1.y, s);
        s = fmaf(v1.z, v1.z, s); s = fmaf(v1.w, v1.w, s);
        uint4 o;
        o.x = pack_f16(a * v0.x, a * v0.y); o.y = pack_f16(a * v0.z, a * v0.w);
        o.z = pack_f16(a * v1.x, a * v1.y); o.w = pack_f16(a * v1.z, a * v1.w);
        dst[i] = o;
    }
    // f16 hi/lo split of the squared norm
    const float hf  = __half2float(__float2half_rn(s));
    const float res = s - hf;
    uint4 aug;
    if (is_x) { aug.x = pack_f16(hf, res);   aug.y = pack_f16(1.f, 1.f); }
    else      { aug.x = pack_f16(1.f, 1.f);  aug.y = pack_f16(hf, res);  }
    aug.z = 0u; aug.w = 0u;
    dst[8] = aug;
    dst[9] = make_uint4(0u, 0u, 0u, 0u);
}

// Tile loader: 1280 16B chunks (128 rows x 160B) over 512 threads.
__device__ __forceinline__ void load_tile(uint32_t t0, uint32_t t1,
                                          const char* gsrc, int tid)
{
#pragma unroll
    for (int i = 0; i < 3; i++) {
        const int idx = i * NT + tid;
        if (idx < 1280) {
            const int row = idx / 10;
            const int q   = idx - row * 10;
            const char* src = gsrc + row * RB + q * 16;
            if (q < 8) cp16(t0 + row * 128 + ((q ^ (row & 7)) << 4), src);
            else       cp16(t1addr(t1, row, q - 8), src);
        }
    }
}

// ---------------------------------------------------------------------------
// Pass 2: 512 threads, 4x4 warps of 32x32 tiles; f16 acc == d^2.
// Epilogue staged through PER-WARP smem (no CTA barriers) for coalesced STG.
// ---------------------------------------------------------------------------
__global__ __launch_bounds__(NT, 2)
void dist_kernel(float* __restrict__ out)
{
    extern __shared__ __align__(128) char smem[];
    const uint32_t sb = smem_u32(smem);

    const int tid  = threadIdx.x;
    const int wid  = tid >> 5;
    const int lane = tid & 31;
    const int qid  = lane >> 2;     // 0..7
    const int t4   = lane & 3;      // 0..3

    const int g     = blockIdx.z;
    const int k0    = blockIdx.x * TN;
    const int bslab = blockIdx.y * (TM * NBT);

    const char* cgb = (const char*)g_cb + (size_t)(g * Kn + k0)    * RB;
    const char* xgb = (const char*)g_xb + (size_t)(g * Bn + bslab) * RB;

    // ---- Prologue: c tile, then x tile 0. ----
    load_tile(sb + CS0, sb + CS1, cgb, tid);
    CP_COMMIT();
    load_tile(sb + XB0, sb + XB0 + 16384, xgb, tid);
    CP_COMMIT();

    const int wm = (wid >> 2) * 32;   // warp m-base: 0/32/64/96
    const int wn = (wid & 3) * 32;    // warp n-base: 0/32/64/96

    // Per-lane ldmatrix geometry.
    const int swz    = lane & 7;
    const int a_row  = lane & 15;                        // + wm + mt*16
    const int a_qoff = lane >> 4;                        // 0/1
    const int b_nrow = ((lane >> 4) << 3) + (lane & 7);  // + wn (+16)
    const int b_qoff = (lane >> 3) & 1;                  // 0/1

    // Per-warp epilogue staging slab: 32 rows x 64B (f16), 2KB.
    const uint32_t wstg = sb + STG_OFF + wid * 2048;
    const int r_lo = lane >> 3;   // reader row within group of 4
    const int c_rd = lane & 7;    // reader 8B chunk

    for (int bt = 0; bt < NBT; bt++) {
        CP_WAIT0();
        __syncthreads();

        if (bt + 1 < NBT) {
            const char* xn = xgb + (size_t)(bt + 1) * TM * RB;
            const uint32_t base = sb + (((bt + 1) & 1) ? XB1 : XB0);
            load_tile(base, base + 16384, xn, tid);
            CP_COMMIT();
        }

        const uint32_t xs0 = sb + ((bt & 1) ? XB1 : XB0);
        const uint32_t xs1 = xs0 + 16384;
        const uint32_t cs0 = sb + CS0;
        const uint32_t cs1 = sb + CS1;

        // acc[mt][nt][h]: f16x2 pair; rows wm+16mt+8h+qid, cols wn+8nt+2t4.
        uint32_t acc[2][4][2];
#pragma unroll
        for (int mt = 0; mt < 2; mt++)
#pragma unroll
            for (int nt = 0; nt < 4; nt++) { acc[mt][nt][0] = 0u; acc[mt][nt][1] = 0u; }

        // ---- k-steps 0..3: main 64 dims. ----
#pragma unroll
        for (int ks = 0; ks < 4; ks++) {
            const uint32_t qa = (uint32_t)(((2 * ks + a_qoff) ^ swz) << 4);
            const uint32_t qb = (uint32_t)(((2 * ks + b_qoff) ^ swz) << 4);

            uint32_t bf[4][2];
            {
                uint32_t r[4];
                ldsm_x4(r, cs0 + (uint32_t)((wn + b_nrow) * 128) + qb);
                bf[0][0] = r[0]; bf[0][1] = r[1]; bf[1][0] = r[2]; bf[1][1] = r[3];
                ldsm_x4(r, cs0 + (uint32_t)((wn + 16 + b_nrow) * 128) + qb);
                bf[2][0] = r[0]; bf[2][1] = r[1]; bf[3][0] = r[2]; bf[3][1] = r[3];
            }
#pragma unroll
            for (int mt = 0; mt < 2; mt++) {
                uint32_t a[4];
                ldsm_x4(a, xs0 + (uint32_t)((wm + mt * 16 + a_row) * 128) + qa);
#pragma unroll
                for (int nt = 0; nt < 4; nt++)
                    mma_f16(acc[mt][nt], a, bf[nt][0], bf[nt][1]);
            }
        }

        // ---- k-step 4: augmented 16 dims. ----
        {
            uint32_t bf[4][2];
            {
                uint32_t r[4];
                ldsm_x4(r, t1addr(cs1, wn + b_nrow, b_qoff));
                bf[0][0] = r[0]; bf[0][1] = r[1]; bf[1][0] = r[2]; bf[1][1] = r[3];
                ldsm_x4(r, t1addr(cs1, wn + 16 + b_nrow, b_qoff));
                bf[2][0] = r[0]; bf[2][1] = r[1]; bf[3][0] = r[2]; bf[3][1] = r[3];
            }
#pragma unroll
            for (int mt = 0; mt < 2; mt++) {
                uint32_t a[4];
                ldsm_x4(a, t1addr(xs1, wm + mt * 16 + a_row, a_qoff));
#pragma unroll
                for (int nt = 0; nt < 4; nt++)
                    mma_f16(acc[mt][nt], a, bf[nt][0], bf[nt][1]);
            }
        }

        // ---- Epilogue: per-warp smem stage -> coalesced sqrt+store. ----
        const int b0 = bslab + bt * TM;

        // Writer: 16 STS.32; position of 4B unit u = 4nt+t4 in row lrow
        // is u ^ (2*qid)  (bijective onto 32 banks per instruction).
#pragma unroll
        for (int mt = 0; mt < 2; mt++)
#pragma unroll
            for (int h = 0; h < 2; h++) {
                const int lrow = 16 * mt + 8 * h + qid;
#pragma unroll
                for (int nt = 0; nt < 4; nt++) {
                    const uint32_t a = wstg + (uint32_t)(lrow * 64 +
                                       (((4 * nt + t4) ^ (2 * qid)) << 2));
                    asm volatile("st.shared.b32 [%0], %1;"
                                 :: "r"(a), "r"(acc[mt][nt][h]) : "memory");
                }
            }
        __syncwarp();

        // Reader: 8 x (LDS.64 + 4 sqrt + STG.128); each STG instruction
        // covers 4 rows x 128B full lines.
#pragma unroll
        for (int it = 0; it < 8; it++) {
            const int lrow = it * 4 + r_lo;
            uint2 v;
            const uint32_t a = wstg + (uint32_t)(lrow * 64 +
                               ((c_rd ^ (lrow & 7)) << 3));
            asm volatile("ld.shared.v2.b32 {%0,%1}, [%2];"
                         : "=r"(v.x), "=r"(v.y) : "r"(a));
            __half2 h0, h1;
            memcpy(&h0, &v.x, 4);
            memcpy(&h1, &v.y, 4);
            const float2 f0 = __half22float2(h0);
            const float2 f1 = __half22float2(h1);
            float* op = out + (size_t)(g * Bn + b0 + wm + lrow) * Kn
                            + k0 + wn + 4 * c_rd;
            stg_cs4(op, fsqrt_approx(f0.x), fsqrt_approx(f0.y),
                        fsqrt_approx(f1.x), fsqrt_approx(f1.y));
        }
        __syncwarp();   // staging slab reusable next tile
    }
}

extern "C" void kernel_launch(void* const* d_in, const int* in_sizes, int n_in,
                              void* d_out, int out_size)
{
    const float* x   = (const float*)d_in[0];   // [G, B, D] fp32
    const float* cen = (const float*)d_in[1];   // [G, K, D] fp32
    float* out = (float*)d_out;                 // [G, B, K] fp32

    static bool attr_set = false;
    if (!attr_set) {
        cudaFuncSetAttribute(dist_kernel,
                             cudaFuncAttributeMaxDynamicSharedMemorySize, SMEM_TOTAL);
        attr_set = true;
    }

    const int nrows = Gn * Bn + Gn * Kn;
    prep_kernel<<<(nrows + 255) / 256, 256>>>(x, cen);

    dim3 grid(Kn / TN, Bn / (TM * NBT), Gn);    // (8, 16, 16) = 2048 CTAs
    dist_kernel<<<grid, NT, SMEM_TOTAL>>>(out);
}